// round 1
// baseline (speedup 1.0000x reference)
#include <cuda_runtime.h>
#include <cuda_bf16.h>
#include <math.h>
#include <math_constants.h>

// Problem constants
#define BQ  8
#define HQ  8
#define BH  64          // B*H
#define LQ  2048
#define DQ  64
#define NSEL 40         // num selected queries == num sampled keys
#define SCALE 0.125f    // 64^-0.5
#define NEG_INF (-CUDART_INF_F)

// ---------------- scratch (device globals; no allocation allowed) ----------
__device__ float g_measure[BH * LQ];
__device__ int   g_topidx[BH * NSEL];
__device__ float g_rowMaxPart[BH * 8 * NSEL];
__device__ float g_rowSumPart[BH * 8 * NSEL];
__device__ float g_rowMax[BH * NSEL];
__device__ float g_rowInv[BH * NSEL];
__device__ float g_outSel[BH * NSEL * DQ];
__device__ float g_chunkSum[BH * 16 * DQ];

// ============================================================================
// K1: measure[bh][i] = max_j (q_i . k_{ridx[i,j]}) - (sum_j ...) / L
// warp per query. q/k rows read as float2 per lane, butterfly reduce.
// ============================================================================
__global__ void k_measure(const float* __restrict__ q,
                          const float* __restrict__ k,
                          const int* __restrict__ ridx) {
    int warp = (blockIdx.x * blockDim.x + threadIdx.x) >> 5;
    int lane = threadIdx.x & 31;
    int bh = warp >> 11;
    int i  = warp & 2047;

    const float2* q2 = reinterpret_cast<const float2*>(q) + ((size_t)(bh * LQ + i)) * 32;
    float2 qv = q2[lane];
    const float2* kb = reinterpret_cast<const float2*>(k) + (size_t)bh * LQ * 32;

    float m = NEG_INF;
    float s = 0.0f;
#pragma unroll 4
    for (int j = 0; j < NSEL; j++) {
        int kj = ridx[i * NSEL + j];
        float2 kv = kb[(size_t)kj * 32 + lane];
        float d = qv.x * kv.x + qv.y * kv.y;
        d += __shfl_xor_sync(0xffffffffu, d, 16);
        d += __shfl_xor_sync(0xffffffffu, d, 8);
        d += __shfl_xor_sync(0xffffffffu, d, 4);
        d += __shfl_xor_sync(0xffffffffu, d, 2);
        d += __shfl_xor_sync(0xffffffffu, d, 1);
        m = fmaxf(m, d);
        s += d;
    }
    if (lane == 0) g_measure[warp] = m - s * (1.0f / (float)LQ);
}

// ============================================================================
// K2: per (b,h) top-40 of 2048 measures, descending, ties -> lower index first
// (matches jax.lax.top_k ordering). One block per bh.
// ============================================================================
__global__ void k_topk() {
    __shared__ float vals[LQ];
    __shared__ float rv[256];
    __shared__ int   ri[256];
    int bh = blockIdx.x;
    int t  = threadIdx.x;

    for (int e = t; e < LQ; e += 256) vals[e] = g_measure[bh * LQ + e];
    __syncthreads();

    for (int r = 0; r < NSEL; r++) {
        float bv = NEG_INF;
        int   bi = LQ;   // sentinel larger than any index
        for (int e = t; e < LQ; e += 256) {
            float v = vals[e];
            if (v > bv || (v == bv && e < bi)) { bv = v; bi = e; }
        }
        rv[t] = bv; ri[t] = bi;
        __syncthreads();
        for (int stride = 128; stride > 0; stride >>= 1) {
            if (t < stride) {
                float v2 = rv[t + stride]; int i2 = ri[t + stride];
                if (v2 > rv[t] || (v2 == rv[t] && i2 < ri[t])) { rv[t] = v2; ri[t] = i2; }
            }
            __syncthreads();
        }
        if (t == 0) {
            g_topidx[bh * NSEL + r] = ri[0];
            vals[ri[0]] = NEG_INF;
        }
        __syncthreads();
    }
}

// ============================================================================
// K3: logits = (q_sel @ k^T)*SCALE with causal mask (j > idx -> -inf),
// written to attn buffer; also per-row partial max / sumexp per 256-key split.
// grid (BH, 8), block 256. Register-tiled 40x128 per subtile.
// ============================================================================
__global__ void k_logits(const float* __restrict__ q,
                         const float* __restrict__ k,
                         float* __restrict__ attn) {
    __shared__ float qs[NSEL * DQ];        // 40x64
    __shared__ float ks[128 * 65];         // padded
    __shared__ int   sidx[NSEL];

    int bh = blockIdx.x, js = blockIdx.y, t = threadIdx.x;
    if (t < NSEL) sidx[t] = g_topidx[bh * NSEL + t];
    __syncthreads();

    for (int e = t; e < NSEL * DQ; e += 256) {
        int s = e >> 6, d = e & 63;
        qs[e] = q[((size_t)bh * LQ + sidx[s]) * DQ + d];
    }

    float* attnBH = attn + (size_t)bh * NSEL * LQ;
    int tx = t & 63, ty = t >> 6;   // tx: key col base, ty: 0..3 row group

    for (int sub = 0; sub < 2; sub++) {
        int j0 = js * 256 + sub * 128;
        __syncthreads();
        for (int e = t; e < 128 * DQ; e += 256) {
            int r = e >> 6, d = e & 63;
            ks[r * 65 + d] = k[((size_t)bh * LQ + j0 + r) * DQ + d];
        }
        __syncthreads();

        float acc[10][2];
#pragma unroll
        for (int r = 0; r < 10; r++) { acc[r][0] = 0.0f; acc[r][1] = 0.0f; }

#pragma unroll 4
        for (int d = 0; d < DQ; d++) {
            float k0 = ks[tx * 65 + d];
            float k1 = ks[(tx + 64) * 65 + d];
#pragma unroll
            for (int r = 0; r < 10; r++) {
                float qv = qs[(ty + 4 * r) * DQ + d];
                acc[r][0] = fmaf(qv, k0, acc[r][0]);
                acc[r][1] = fmaf(qv, k1, acc[r][1]);
            }
        }
#pragma unroll
        for (int r = 0; r < 10; r++) {
            int s = ty + 4 * r;
            int lim = sidx[s];
            int jg0 = j0 + tx;
            int jg1 = j0 + tx + 64;
            attnBH[(size_t)s * LQ + jg0] = (jg0 > lim) ? NEG_INF : acc[r][0] * SCALE;
            attnBH[(size_t)s * LQ + jg1] = (jg1 > lim) ? NEG_INF : acc[r][1] * SCALE;
        }
    }
    __syncthreads();   // make our global logit writes visible block-wide

    // partial softmax stats over this block's 256-key span
    int w = t >> 5, lane = t & 31;
    for (int rr = 0; rr < 5; rr++) {
        int s = w + 8 * rr;
        size_t base = (size_t)s * LQ + js * 256;
        float m = NEG_INF;
#pragma unroll
        for (int u = 0; u < 8; u++) m = fmaxf(m, attnBH[base + lane + 32 * u]);
        m = fmaxf(m, __shfl_xor_sync(0xffffffffu, m, 16));
        m = fmaxf(m, __shfl_xor_sync(0xffffffffu, m, 8));
        m = fmaxf(m, __shfl_xor_sync(0xffffffffu, m, 4));
        m = fmaxf(m, __shfl_xor_sync(0xffffffffu, m, 2));
        m = fmaxf(m, __shfl_xor_sync(0xffffffffu, m, 1));
        float ssum = 0.0f;
        if (m > NEG_INF) {
#pragma unroll
            for (int u = 0; u < 8; u++) ssum += expf(attnBH[base + lane + 32 * u] - m);
        }
        ssum += __shfl_xor_sync(0xffffffffu, ssum, 16);
        ssum += __shfl_xor_sync(0xffffffffu, ssum, 8);
        ssum += __shfl_xor_sync(0xffffffffu, ssum, 4);
        ssum += __shfl_xor_sync(0xffffffffu, ssum, 2);
        ssum += __shfl_xor_sync(0xffffffffu, ssum, 1);
        if (lane == 0) {
            g_rowMaxPart[(bh * 8 + js) * NSEL + s] = m;
            g_rowSumPart[(bh * 8 + js) * NSEL + s] = ssum;
        }
    }
}

// ============================================================================
// K3b: combine partial stats -> final rowMax / 1/rowSum; zero outSel scratch
// grid BH, block 64
// ============================================================================
__global__ void k_combine() {
    int bh = blockIdx.x, t = threadIdx.x;
    if (t < NSEL) {
        float fm = NEG_INF;
#pragma unroll
        for (int p = 0; p < 8; p++)
            fm = fmaxf(fm, g_rowMaxPart[(bh * 8 + p) * NSEL + t]);
        float fs = 0.0f;
#pragma unroll
        for (int p = 0; p < 8; p++) {
            float pm = g_rowMaxPart[(bh * 8 + p) * NSEL + t];
            float ps = g_rowSumPart[(bh * 8 + p) * NSEL + t];
            fs += ps * expf(pm - fm);   // pm=-inf -> ps==0 and expf(-inf)=0 -> 0
        }
        g_rowMax[bh * NSEL + t] = fm;
        g_rowInv[bh * NSEL + t] = 1.0f / fs;
    }
    for (int e = t; e < NSEL * DQ; e += 64) g_outSel[bh * NSEL * DQ + e] = 0.0f;
}

// ============================================================================
// cumsum(v, axis=L): 3-pass chunk scan (chunk = 128 rows, 16 chunks)
// ============================================================================
__global__ void k_csumA(const float* __restrict__ v) {       // grid (BH,16), 256 thr
    int bh = blockIdx.x, c = blockIdx.y, t = threadIdx.x;
    int d = t & 63, g = t >> 6;
    const float* base = v + ((size_t)bh * LQ + c * 128) * DQ;
    float s = 0.0f;
#pragma unroll 8
    for (int r = g * 32; r < g * 32 + 32; r++) s += base[(size_t)r * DQ + d];
    __shared__ float red[256];
    red[t] = s;
    __syncthreads();
    if (g == 0)
        g_chunkSum[(bh * 16 + c) * DQ + d] = red[d] + red[64 + d] + red[128 + d] + red[192 + d];
}

__global__ void k_csumB() {                                  // grid BH, 64 thr
    int bh = blockIdx.x, d = threadIdx.x;
    float run = 0.0f;
#pragma unroll
    for (int c = 0; c < 16; c++) {
        float x = g_chunkSum[(bh * 16 + c) * DQ + d];
        g_chunkSum[(bh * 16 + c) * DQ + d] = run;   // exclusive
        run += x;
    }
}

__global__ void k_csumC(const float* __restrict__ v, float* __restrict__ out) { // grid (BH,16), 64 thr
    int bh = blockIdx.x, c = blockIdx.y, d = threadIdx.x;
    const float* base = v + ((size_t)bh * LQ + c * 128) * DQ;
    float* obase = out + ((size_t)bh * LQ + c * 128) * DQ;
    float run = g_chunkSum[(bh * 16 + c) * DQ + d];
#pragma unroll 8
    for (int r = 0; r < 128; r++) {
        run += base[(size_t)r * DQ + d];
        obase[(size_t)r * DQ + d] = run;
    }
}

// ============================================================================
// K4: probs = softmax(logits) written in place to attn; out_sel += P @ V
// grid (BH, 4 jsplits of 512 keys), block 256. 8 inner tiles of 64 keys.
// ============================================================================
__global__ void k_pv(const float* __restrict__ v, float* __restrict__ attn) {
    __shared__ float vs[64 * DQ];     // 16 KB
    __shared__ float ps[NSEL * 64];   // 10 KB
    __shared__ float sMax[NSEL], sInv[NSEL];

    int bh = blockIdx.x, js = blockIdx.y, t = threadIdx.x;
    if (t < NSEL) { sMax[t] = g_rowMax[bh * NSEL + t]; sInv[t] = g_rowInv[bh * NSEL + t]; }

    float* attnBH = attn + (size_t)bh * NSEL * LQ;
    const float* vBH = v + (size_t)bh * LQ * DQ;

    int tx = t & 31, ty = t >> 5;
    int g = ty >> 2;       // jj half: 0 or 1 (32 keys each)
    int sy = ty & 3;       // row group: s = sy + 4r

    float acc[10][2];
#pragma unroll
    for (int r = 0; r < 10; r++) { acc[r][0] = 0.0f; acc[r][1] = 0.0f; }
    __syncthreads();

    for (int tile = 0; tile < 8; tile++) {
        int j0 = js * 512 + tile * 64;
        __syncthreads();
        // load V tile (64 x 64)
        const float4* vsrc = reinterpret_cast<const float4*>(vBH + (size_t)j0 * DQ);
        float4* vdst = reinterpret_cast<float4*>(vs);
        for (int e = t; e < 64 * DQ / 4; e += 256) vdst[e] = vsrc[e];
        // compute probs, write back to attn, stage in smem
        for (int e = t; e < NSEL * 64; e += 256) {
            int s = e >> 6, jj = e & 63;
            size_t a = (size_t)s * LQ + j0 + jj;
            float l = attnBH[a];
            float p = expf(l - sMax[s]) * sInv[s];
            attnBH[a] = p;
            ps[e] = p;
        }
        __syncthreads();
#pragma unroll 4
        for (int jl = g * 32; jl < g * 32 + 32; jl++) {
            float2 vv = *reinterpret_cast<const float2*>(&vs[jl * DQ + 2 * tx]);
#pragma unroll
            for (int r = 0; r < 10; r++) {
                float p = ps[(sy + 4 * r) * 64 + jl];
                acc[r][0] = fmaf(p, vv.x, acc[r][0]);
                acc[r][1] = fmaf(p, vv.y, acc[r][1]);
            }
        }
    }
#pragma unroll
    for (int r = 0; r < 10; r++) {
        int s = sy + 4 * r;
        atomicAdd(&g_outSel[(bh * NSEL + s) * DQ + 2 * tx], acc[r][0]);
        atomicAdd(&g_outSel[(bh * NSEL + s) * DQ + 2 * tx + 1], acc[r][1]);
    }
}

// ============================================================================
// K6: scatter out_sel rows into out at the selected positions
// ============================================================================
__global__ void k_scatter(float* __restrict__ out) {   // grid BH, 256 thr
    int bh = blockIdx.x, t = threadIdx.x;
    for (int e = t; e < NSEL * DQ; e += 256) {
        int s = e >> 6, d = e & 63;
        out[((size_t)bh * LQ + g_topidx[bh * NSEL + s]) * DQ + d] =
            g_outSel[bh * NSEL * DQ + e];
    }
}

// ============================================================================
extern "C" void kernel_launch(void* const* d_in, const int* in_sizes, int n_in,
                              void* d_out, int out_size) {
    const float* q = (const float*)d_in[0];
    const float* k = (const float*)d_in[1];
    const float* v = (const float*)d_in[2];
    const int* ridx = (const int*)d_in[3];

    float* out  = (float*)d_out;                        // [BH, L, D]
    float* attn = out + (size_t)BH * LQ * DQ;           // [BH, NSEL, L]

    // 1. measure
    k_measure<<<(BH * LQ) / 8, 256>>>(q, k, ridx);
    // 2. top-k selection
    k_topk<<<BH, 256>>>();
    // 3. logits + partial softmax stats
    {
        dim3 grid(BH, 8);
        k_logits<<<grid, 256>>>(q, k, attn);
    }
    // 3b. combine stats, zero out_sel
    k_combine<<<BH, 64>>>();
    // 5. cumsum(v) -> out
    {
        dim3 grid(BH, 16);
        k_csumA<<<grid, 256>>>(v);
        k_csumB<<<BH, 64>>>();
        k_csumC<<<grid, 64>>>(v, out);
    }
    // 4. softmax probs (in place) + P@V partial accumulation
    {
        dim3 grid(BH, 4);
        k_pv<<<grid, 256>>>(v, attn);
    }
    // 6. scatter selected rows into out
    k_scatter<<<BH, 256>>>(out);
}